// round 15
// baseline (speedup 1.0000x reference)
#include <cuda_runtime.h>
#include <cstdint>

// Problem constants
#define NB 64
#define NN 4096
#define NF 256
#define ND 128
#define NSLOT 8
#define NCH 32                  // block-chunks per batch (128 rows each)

typedef unsigned long long u64t;

// ---------------- device scratch ----------------
__device__ float g_part[(size_t)NB*NCH*NSLOT*NF];   // [b][c][k][f]
__device__ float g_t2p[NB*NCH*NSLOT];
__device__ float g_t3p[NB*NCH*NSLOT];
__device__ float g_c1[NB*NSLOT*NF];                 // lw * q'   [b][k][f]
__device__ float g_c2[NB*NSLOT];
__device__ float g_c3[NB*NSLOT];
__device__ float2 g_stats[(size_t)NB*NN];           // {mu, rs} per row

__device__ __forceinline__ float sigm(float x){ return 1.f / (1.f + expf(-x)); }

// packed f32x2 helpers (Blackwell FFMA2 path; ptxas never auto-fuses)
__device__ __forceinline__ u64t fma2(u64t a, u64t b, u64t c){
  u64t d; asm("fma.rn.f32x2 %0, %1, %2, %3;" : "=l"(d) : "l"(a), "l"(b), "l"(c));
  return d;
}
__device__ __forceinline__ u64t pack2(float lo, float hi){
  u64t r; asm("mov.b64 %0, {%1, %2};" : "=l"(r) : "f"(lo), "f"(hi));
  return r;
}
__device__ __forceinline__ float2 unpack2(u64t v){
  float2 r; asm("mov.b64 {%0, %1}, %2;" : "=f"(r.x), "=f"(r.y) : "l"(v));
  return r;
}

__global__ void dummy_k(){}

// =====================================================================
// stats_k: per-row LN stats, once. Warp per row.
// =====================================================================
__global__ void __launch_bounds__(256) stats_k(const float* __restrict__ X){
  const int warp = threadIdx.x >> 5, lane = threadIdx.x & 31;
  const size_t row = (size_t)blockIdx.x * 8 + warp;
  const float4* xr = (const float4*)(X + row*NF);
  float4 x0 = __ldg(xr + lane);
  float4 x1 = __ldg(xr + 32 + lane);
  float s  = ((x0.x + x0.y) + (x0.z + x0.w)) + ((x1.x + x1.y) + (x1.z + x1.w));
  float q2 = x0.x*x0.x;
  q2 = fmaf(x0.y, x0.y, q2); q2 = fmaf(x0.z, x0.z, q2); q2 = fmaf(x0.w, x0.w, q2);
  q2 = fmaf(x1.x, x1.x, q2); q2 = fmaf(x1.y, x1.y, q2);
  q2 = fmaf(x1.z, x1.z, q2); q2 = fmaf(x1.w, x1.w, q2);
  #pragma unroll
  for (int off = 16; off; off >>= 1){
    s  += __shfl_xor_sync(0xffffffffu, s,  off);
    q2 += __shfl_xor_sync(0xffffffffu, q2, off);
  }
  if (lane == 0){
    float mu = s * (1.f/256.f);
    float rs = rsqrtf(fmaf(q2, 1.f/256.f, -mu*mu) + 1e-5f);
    g_stats[row] = make_float2(mu, rs);
  }
}

// =====================================================================
// attn_scan v8: v6 schedule + packed f32x2 dots/accumulate.
// Grid (NB, 32), 128 threads (4 warps x 32 rows).
// =====================================================================
__global__ void __launch_bounds__(128, 3) attn_scan(const float* __restrict__ X){
  const int b = blockIdx.x, blk = blockIdx.y;
  const int tid = threadIdx.x;
  const int warp = tid >> 5, lane = tid & 31;

  __shared__ __align__(16) float s_c1[NSLOT*NF];      // 8KB
  __shared__ __align__(16) float s_buf[4][NSLOT*NF];  // 32KB
  __shared__ float s_t23[4][16];

  for (int i = tid; i < NSLOT*NF; i += 128) s_c1[i] = __ldg(g_c1 + b*NSLOT*NF + i);
  float c2[NSLOT], c3[NSLOT];
  #pragma unroll
  for (int k = 0; k < NSLOT; k++){
    c2[k] = __ldg(g_c2 + b*NSLOT + k);
    c3[k] = __ldg(g_c3 + b*NSLOT + k);
  }
  __syncthreads();

  // c1 fragments as packed pairs (LDS.128 once, reused across all rows via regs)
  ulonglong2 CA[NSLOT], CB[NSLOT];
  #pragma unroll
  for (int k = 0; k < NSLOT; k++){
    CA[k] = *(const ulonglong2*)(s_c1 + k*NF + lane*4);
    CB[k] = *(const ulonglong2*)(s_c1 + k*NF + 128 + lane*4);
  }

  // packed accumulators: A[k][0..3] <-> float pairs (4l,4l+1),(4l+2,4l+3),(128+4l,..),(..)
  u64t A[NSLOT][4];
  float t2a[NSLOT], t3a[NSLOT];
  #pragma unroll
  for (int k = 0; k < NSLOT; k++){
    A[k][0] = 0ull; A[k][1] = 0ull; A[k][2] = 0ull; A[k][3] = 0ull;
    t2a[k] = 0.f; t3a[k] = 0.f;
  }

  const size_t row0 = (size_t)b*NN + (size_t)blk*128 + (size_t)warp*32;
  const float* Xb = X + row0*NF;

  for (int r = 0; r < 32; r += 2){
    const ulonglong2* xp = (const ulonglong2*)(Xb + (size_t)r*NF);
    ulonglong2 X0 = __ldg(xp + lane);        // row r, floats 4l..4l+3
    ulonglong2 X1 = __ldg(xp + 32 + lane);   // row r, floats 128+4l..
    ulonglong2 Y0 = __ldg(xp + 64 + lane);   // row r+1
    ulonglong2 Y1 = __ldg(xp + 96 + lane);
    float2 stx = __ldg(&g_stats[row0 + r]);
    float2 sty = __ldg(&g_stats[row0 + r + 1]);

    // packed dot partials
    u64t P[NSLOT], Q[NSLOT];
    #pragma unroll
    for (int k = 0; k < NSLOT; k++){
      u64t pk = fma2(X0.x, CA[k].x, 0ull);
      pk = fma2(X0.y, CA[k].y, pk);
      pk = fma2(X1.x, CB[k].x, pk);
      pk = fma2(X1.y, CB[k].y, pk);
      P[k] = pk;
      u64t qk = fma2(Y0.x, CA[k].x, 0ull);
      qk = fma2(Y0.y, CA[k].y, qk);
      qk = fma2(Y1.x, CB[k].x, qk);
      qk = fma2(Y1.y, CB[k].y, qk);
      Q[k] = qk;
    }
    float p[NSLOT], q[NSLOT];
    #pragma unroll
    for (int k = 0; k < NSLOT; k++){
      float2 pp = unpack2(P[k]); p[k] = pp.x + pp.y;
      float2 qq = unpack2(Q[k]); q[k] = qq.x + qq.y;
    }
    #pragma unroll
    for (int off = 16; off; off >>= 1){
      #pragma unroll
      for (int k = 0; k < NSLOT; k++){
        p[k] += __shfl_xor_sync(0xffffffffu, p[k], off);
        q[k] += __shfl_xor_sync(0xffffffffu, q[k], off);
      }
    }

    // row r softmax + packed accumulate
    {
      const float mu = stx.x, rs = stx.y;
      float lg[NSLOT];
      #pragma unroll
      for (int k = 0; k < NSLOT; k++)
        lg[k] = fmaf(rs, fmaf(-mu, c2[k], p[k]), c3[k]);
      float m = fmaxf(fmaxf(fmaxf(lg[0],lg[1]), fmaxf(lg[2],lg[3])),
                      fmaxf(fmaxf(lg[4],lg[5]), fmaxf(lg[6],lg[7])));
      float e[NSLOT], es = 0.f;
      #pragma unroll
      for (int k = 0; k < NSLOT; k++){ e[k] = __expf(lg[k] - m); es += e[k]; }
      float inv = __fdividef(1.f, es);
      #pragma unroll
      for (int k = 0; k < NSLOT; k++){
        float a  = fmaf(e[k], inv, 1e-8f);
        float ar = a * rs;
        t3a[k] += a;
        t2a[k] = fmaf(ar, mu, t2a[k]);
        u64t arp = pack2(ar, ar);
        A[k][0] = fma2(arp, X0.x, A[k][0]);
        A[k][1] = fma2(arp, X0.y, A[k][1]);
        A[k][2] = fma2(arp, X1.x, A[k][2]);
        A[k][3] = fma2(arp, X1.y, A[k][3]);
      }
    }
    // row r+1 softmax + packed accumulate
    {
      const float mu = sty.x, rs = sty.y;
      float lg[NSLOT];
      #pragma unroll
      for (int k = 0; k < NSLOT; k++)
        lg[k] = fmaf(rs, fmaf(-mu, c2[k], q[k]), c3[k]);
      float m = fmaxf(fmaxf(fmaxf(lg[0],lg[1]), fmaxf(lg[2],lg[3])),
                      fmaxf(fmaxf(lg[4],lg[5]), fmaxf(lg[6],lg[7])));
      float e[NSLOT], es = 0.f;
      #pragma unroll
      for (int k = 0; k < NSLOT; k++){ e[k] = __expf(lg[k] - m); es += e[k]; }
      float inv = __fdividef(1.f, es);
      #pragma unroll
      for (int k = 0; k < NSLOT; k++){
        float a  = fmaf(e[k], inv, 1e-8f);
        float ar = a * rs;
        t3a[k] += a;
        t2a[k] = fmaf(ar, mu, t2a[k]);
        u64t arp = pack2(ar, ar);
        A[k][0] = fma2(arp, Y0.x, A[k][0]);
        A[k][1] = fma2(arp, Y0.y, A[k][1]);
        A[k][2] = fma2(arp, Y1.x, A[k][2]);
        A[k][3] = fma2(arp, Y1.y, A[k][3]);
      }
    }
  }

  // block combine: unpack accumulators into per-warp smem buffer
  #pragma unroll
  for (int k = 0; k < NSLOT; k++){
    float2 a0 = unpack2(A[k][0]), a1 = unpack2(A[k][1]);
    float2 a2 = unpack2(A[k][2]), a3 = unpack2(A[k][3]);
    *(float4*)(s_buf[warp] + k*NF + lane*4)       = make_float4(a0.x, a0.y, a1.x, a1.y);
    *(float4*)(s_buf[warp] + k*NF + 128 + lane*4) = make_float4(a2.x, a2.y, a3.x, a3.y);
  }
  if (lane == 0){
    #pragma unroll
    for (int k = 0; k < NSLOT; k++){
      s_t23[warp][k]     = t2a[k];
      s_t23[warp][8 + k] = t3a[k];
    }
  }
  __syncthreads();

  float* gp = g_part + (size_t)((b*NCH + blk)*NSLOT)*NF;
  #pragma unroll
  for (int j = 0; j < 4; j++){
    int off = (tid + j*128) * 4;
    float4 v0 = *(const float4*)(s_buf[0] + off);
    float4 v1 = *(const float4*)(s_buf[1] + off);
    float4 v2 = *(const float4*)(s_buf[2] + off);
    float4 v3 = *(const float4*)(s_buf[3] + off);
    float4 v;
    v.x = (v0.x + v1.x) + (v2.x + v3.x);
    v.y = (v0.y + v1.y) + (v2.y + v3.y);
    v.z = (v0.z + v1.z) + (v2.z + v3.z);
    v.w = (v0.w + v1.w) + (v2.w + v3.w);
    *(float4*)(gp + off) = v;
  }
  if (tid < 16){
    float v = s_t23[0][tid] + s_t23[1][tid] + s_t23[2][tid] + s_t23[3][tid];
    if (tid < 8) g_t2p[(b*NCH + blk)*NSLOT + tid]       = v;
    else         g_t3p[(b*NCH + blk)*NSLOT + (tid - 8)] = v;
  }
}

// =====================================================================
// tail_bk v5 (best measured): 2 slots per block, grid (NB,4), 256 thr.
// =====================================================================
__global__ void __launch_bounds__(256) tail_bk(float* __restrict__ slots,
    const float* __restrict__ wi, const float* __restrict__ wh,
    const float* __restrict__ bi, const float* __restrict__ bh,
    const float* __restrict__ lnw, const float* __restrict__ lnb,   // ln_mlp
    const float* __restrict__ w1, const float* __restrict__ b1,
    const float* __restrict__ w2, const float* __restrict__ b2,
    const float* __restrict__ Wq, const float* __restrict__ Wk,
    const float* __restrict__ Wv,
    const float* __restrict__ lnqw, const float* __restrict__ lnqb, // ln_slots
    const float* __restrict__ liw, const float* __restrict__ lib,   // ln_in
    int do_q){
  const int b = blockIdx.x, kb = blockIdx.y*2, t = threadIdx.x;
  __shared__ float s_wt[2][256];
  __shared__ float s_sp[2][128], s_upd[2][128];
  __shared__ float s_gx[2][384], s_gh[2][384];
  __shared__ float s_mid[2][128], s_ln[2][128], s_h[2][256], s_new[2][128];
  __shared__ __align__(16) float s_q[2][128];
  __shared__ float s_qp[2][256];
  __shared__ float s_red[2][2][128];
  __shared__ float s_sc2[2], s_sc3[2], s_mu[2], s_rs[2];

  {
    int s = t >> 7, d = t & 127;
    s_sp[s][d] = slots[b*1024 + (kb+s)*128 + d];
  }

  if (t < 128){
    int w = t >> 5, lane = t & 31;
    int s = w & 1;
    const float* src = (w < 2) ? g_t2p : g_t3p;
    float a = __ldg(src + (b*NCH + lane)*NSLOT + kb + s);
    #pragma unroll
    for (int off = 16; off; off >>= 1)
      a += __shfl_xor_sync(0xffffffffu, a, off);
    if (lane == 0){
      if (w < 2) s_sc2[s] = a; else s_sc3[s] = a;
    }
  }
  __syncthreads();

  for (int idx = t; idx < 512; idx += 256){
    int k = idx >> 8, f = idx & 255;
    const float* gp = g_part + ((size_t)(b*NCH)*NSLOT + kb + k)*NF + f;
    float acc = 0.f;
    #pragma unroll
    for (int cb = 0; cb < NCH; cb += 16){
      float v[16];
      #pragma unroll
      for (int j = 0; j < 16; j++) v[j] = __ldg(gp + (size_t)(cb+j)*NSLOT*NF);
      #pragma unroll
      for (int j = 0; j < 16; j++) acc += v[j];
    }
    s_wt[k][f] = liw[f]*(acc - s_sc2[k]) + lib[f]*s_sc3[k];
  }
  __syncthreads();

  {
    int d = t & 127, h = t >> 7;
    float u0 = 0.f, u1 = 0.f;
    for (int fb = h*128; fb < h*128 + 128; fb += 16){
      float v[16];
      #pragma unroll
      for (int j = 0; j < 16; j++) v[j] = __ldg(Wv + (fb+j)*128 + d);
      #pragma unroll
      for (int j = 0; j < 16; j++){
        u0 = fmaf(s_wt[0][fb+j], v[j], u0);
        u1 = fmaf(s_wt[1][fb+j], v[j], u1);
      }
    }
    s_red[h][0][d] = u0; s_red[h][1][d] = u1;
  }
  __syncthreads();
  {
    int k = t >> 7, d = t & 127;
    s_upd[k][d] = (s_red[0][k][d] + s_red[1][k][d]) / s_sc3[k];
  }
  __syncthreads();

  #pragma unroll
  for (int pass = 0; pass < 2; pass++){
    int g = pass ? (256 + t) : t;
    if (g < 384){
      float ax0 = bi[g], ah0 = bh[g];
      float ax1 = ax0, ah1 = ah0;
      for (int fb = 0; fb < 128; fb += 16){
        float a_[16], h_[16];
        #pragma unroll
        for (int j = 0; j < 16; j++){
          a_[j] = __ldg(wi + (fb+j)*384 + g);
          h_[j] = __ldg(wh + (fb+j)*384 + g);
        }
        #pragma unroll
        for (int j = 0; j < 16; j++){
          ax0 = fmaf(s_upd[0][fb+j], a_[j], ax0);
          ah0 = fmaf(s_sp[0][fb+j],  h_[j], ah0);
          ax1 = fmaf(s_upd[1][fb+j], a_[j], ax1);
          ah1 = fmaf(s_sp[1][fb+j],  h_[j], ah1);
        }
      }
      s_gx[0][g] = ax0; s_gh[0][g] = ah0;
      s_gx[1][g] = ax1; s_gh[1][g] = ah1;
    }
  }
  __syncthreads();

  {
    int k = t >> 7, d = t & 127;
    float r = sigm(s_gx[k][d] + s_gh[k][d]);
    float z = sigm(s_gx[k][128 + d] + s_gh[k][128 + d]);
    float n = tanhf(fmaf(r, s_gh[k][256 + d], s_gx[k][256 + d]));
    s_mid[k][d] = (1.f - z)*n + z*s_sp[k][d];
  }
  __syncthreads();

  if (t < 64){
    int s = t >> 5, lane = t & 31;
    float xs = 0.f, xq = 0.f;
    #pragma unroll
    for (int i = 0; i < 4; i++){
      float x = s_mid[s][lane + i*32];
      xs += x; xq = fmaf(x, x, xq);
    }
    #pragma unroll
    for (int off = 16; off; off >>= 1){
      xs += __shfl_xor_sync(0xffffffffu, xs, off);
      xq += __shfl_xor_sync(0xffffffffu, xq, off);
    }
    if (lane == 0){
      float mu = xs * (1.f/128.f);
      s_mu[s] = mu; s_rs[s] = rsqrtf(xq*(1.f/128.f) - mu*mu + 1e-5f);
    }
  }
  __syncthreads();
  {
    int k = t >> 7, d = t & 127;
    s_ln[k][d] = (s_mid[k][d] - s_mu[k])*s_rs[k]*lnw[d] + lnb[d];
  }
  __syncthreads();

  {
    int c = t;
    float h0 = b1[c], h1 = h0;
    for (int fb = 0; fb < 128; fb += 16){
      float v[16];
      #pragma unroll
      for (int j = 0; j < 16; j++) v[j] = __ldg(w1 + (fb+j)*256 + c);
      #pragma unroll
      for (int j = 0; j < 16; j++){
        h0 = fmaf(s_ln[0][fb+j], v[j], h0);
        h1 = fmaf(s_ln[1][fb+j], v[j], h1);
      }
    }
    s_h[0][c] = fmaxf(h0, 0.f); s_h[1][c] = fmaxf(h1, 0.f);
  }
  __syncthreads();

  {
    int d = t & 127, h = t >> 7;
    float o0 = 0.f, o1 = 0.f;
    for (int cb = h*128; cb < h*128 + 128; cb += 16){
      float v[16];
      #pragma unroll
      for (int j = 0; j < 16; j++) v[j] = __ldg(w2 + (cb+j)*128 + d);
      #pragma unroll
      for (int j = 0; j < 16; j++){
        o0 = fmaf(s_h[0][cb+j], v[j], o0);
        o1 = fmaf(s_h[1][cb+j], v[j], o1);
      }
    }
    s_red[h][0][d] = o0; s_red[h][1][d] = o1;
  }
  __syncthreads();
  {
    int k = t >> 7, d = t & 127;
    float o = s_mid[k][d] + b2[d] + s_red[0][k][d] + s_red[1][k][d];
    slots[b*1024 + (kb+k)*128 + d] = o;
    s_new[k][d] = o;
  }
  if (!do_q) return;
  __syncthreads();

  if (t < 64){
    int s = t >> 5, lane = t & 31;
    float xs = 0.f, xq = 0.f;
    #pragma unroll
    for (int i = 0; i < 4; i++){
      float x = s_new[s][lane + i*32];
      xs += x; xq = fmaf(x, x, xq);
    }
    #pragma unroll
    for (int off = 16; off; off >>= 1){
      xs += __shfl_xor_sync(0xffffffffu, xs, off);
      xq += __shfl_xor_sync(0xffffffffu, xq, off);
    }
    if (lane == 0){
      float mu = xs * (1.f/128.f);
      s_mu[s] = mu; s_rs[s] = rsqrtf(xq*(1.f/128.f) - mu*mu + 1e-5f);
    }
  }
  __syncthreads();
  {
    int k = t >> 7, d = t & 127;
    s_ln[k][d] = (s_new[k][d] - s_mu[k])*s_rs[k]*lnqw[d] + lnqb[d];
  }
  __syncthreads();

  {
    int d = t & 127, h = t >> 7;
    float a0 = 0.f, a1 = 0.f;
    for (int fb = h*64; fb < h*64 + 64; fb += 16){
      float v[16];
      #pragma unroll
      for (int j = 0; j < 16; j++) v[j] = __ldg(Wq + (fb+j)*128 + d);
      #pragma unroll
      for (int j = 0; j < 16; j++){
        a0 = fmaf(s_ln[0][fb+j], v[j], a0);
        a1 = fmaf(s_ln[1][fb+j], v[j], a1);
      }
    }
    s_red[h][0][d] = a0; s_red[h][1][d] = a1;
  }
  __syncthreads();
  {
    int k = t >> 7, d = t & 127;
    s_q[k][d] = (s_red[0][k][d] + s_red[1][k][d]) * 0.08838834764831845f;
  }
  __syncthreads();

  {
    int w = t >> 5, lane = t & 31;
    float4 qv0 = *((const float4*)s_q[0] + lane);
    float4 qv1 = *((const float4*)s_q[1] + lane);
    for (int i = 0; i < 32; i += 4){
      float pp[8];
      #pragma unroll
      for (int j = 0; j < 4; j++){
        int f = w*32 + i + j;
        float4 wk = __ldg((const float4*)(Wk + f*128) + lane);
        float v0 = wk.x*qv0.x;
        v0 = fmaf(wk.y, qv0.y, v0);
        v0 = fmaf(wk.z, qv0.z, v0);
        v0 = fmaf(wk.w, qv0.w, v0);
        pp[j] = v0;
        float v1 = wk.x*qv1.x;
        v1 = fmaf(wk.y, qv1.y, v1);
        v1 = fmaf(wk.z, qv1.z, v1);
        v1 = fmaf(wk.w, qv1.w, v1);
        pp[4+j] = v1;
      }
      #pragma unroll
      for (int off = 16; off; off >>= 1)
        #pragma unroll
        for (int j = 0; j < 8; j++)
          pp[j] += __shfl_xor_sync(0xffffffffu, pp[j], off);
      if (lane == 0){
        #pragma unroll
        for (int j = 0; j < 4; j++){
          int f = w*32 + i + j;
          s_qp[0][f] = pp[j];
          s_qp[1][f] = pp[4+j];
          g_c1[b*2048 + kb*256 + f]       = liw[f] * pp[j];
          g_c1[b*2048 + (kb+1)*256 + f]   = liw[f] * pp[4+j];
        }
      }
    }
  }
  __syncthreads();

  if (t < 64){
    int s = t >> 5, lane = t & 31;
    float a2 = 0.f, a3 = 0.f;
    #pragma unroll
    for (int i = 0; i < 8; i++){
      int f = lane + i*32;
      a2 = fmaf(liw[f], s_qp[s][f], a2);
      a3 = fmaf(lib[f], s_qp[s][f], a3);
    }
    #pragma unroll
    for (int off = 16; off; off >>= 1){
      a2 += __shfl_xor_sync(0xffffffffu, a2, off);
      a3 += __shfl_xor_sync(0xffffffffu, a3, off);
    }
    if (lane == 0){
      g_c2[b*NSLOT + kb + s] = a2;
      g_c3[b*NSLOT + kb + s] = a3;
    }
  }
}

// =====================================================================
// qprep0: init slots + first-iteration c1/c2/c3 (batched loads)
// =====================================================================
__global__ void __launch_bounds__(384) qprep0(const float* __restrict__ si,
    float* __restrict__ slots,
    const float* __restrict__ Wq, const float* __restrict__ Wk,
    const float* __restrict__ lnqw, const float* __restrict__ lnqb,
    const float* __restrict__ liw, const float* __restrict__ lib){
  const int b = blockIdx.x, t = threadIdx.x;
  __shared__ float s_new[1024], s_lnq[1024], s_q[1024], s_qp[2048];
  __shared__ float smu[NSLOT], srs[NSLOT];
  for (int idx = t; idx < 1024; idx += 384){
    float v = si[idx];
    s_new[idx] = v;
    slots[b*1024 + idx] = v;
  }
  __syncthreads();
  if (t < NSLOT){
    float su = 0.f, sq = 0.f;
    for (int d = 0; d < ND; d++){ float x = s_new[t*ND + d]; su += x; sq = fmaf(x,x,sq); }
    float mu = su * (1.f/ND);
    smu[t] = mu; srs[t] = rsqrtf(sq*(1.f/ND) - mu*mu + 1e-5f);
  }
  __syncthreads();
  for (int idx = t; idx < 1024; idx += 384){
    int j = idx >> 7, d = idx & 127;
    s_lnq[idx] = (s_new[idx] - smu[j]) * srs[j] * lnqw[d] + lnqb[d];
  }
  __syncthreads();
  const float inv_scale = 0.08838834764831845f;
  for (int idx = t; idx < 1024; idx += 384){
    int j = idx >> 7, d = idx & 127;
    float a = 0.f;
    for (int fb = 0; fb < 128; fb += 8){
      float v[8];
      #pragma unroll
      for (int u = 0; u < 8; u++) v[u] = __ldg(Wq + (fb+u)*128 + d);
      #pragma unroll
      for (int u = 0; u < 8; u++) a = fmaf(s_lnq[j*128 + fb+u], v[u], a);
    }
    s_q[idx] = a * inv_scale;
  }
  __syncthreads();
  for (int idx = t; idx < 2048; idx += 384){
    int k = idx >> 8, f = idx & 255;
    float qp = 0.f;
    const float* qrow = s_q + k*128;
    const float* wrow = Wk + f*128;
    for (int fb = 0; fb < 128; fb += 8){
      float v[8];
      #pragma unroll
      for (int u = 0; u < 8; u++) v[u] = __ldg(wrow + fb + u);
      #pragma unroll
      for (int u = 0; u < 8; u++) qp = fmaf(qrow[fb+u], v[u], qp);
    }
    s_qp[idx] = qp;
    g_c1[b*2048 + idx] = liw[f] * qp;
  }
  __syncthreads();
  if (t < NSLOT){
    float a2 = 0.f, a3 = 0.f;
    for (int f = 0; f < 256; f++){
      a2 = fmaf(liw[f], s_qp[t*256 + f], a2);
      a3 = fmaf(lib[f], s_qp[t*256 + f], a3);
    }
    g_c2[b*NSLOT + t] = a2;
    g_c3[b*NSLOT + t] = a3;
  }
}

// ---------------- launch ----------------
extern "C" void kernel_launch(void* const* d_in, const int* in_sizes, int n_in,
                              void* d_out, int out_size){
  const float* inputs   = (const float*)d_in[0];
  const float* slotinit = (const float*)d_in[1];
  const float* Wq       = (const float*)d_in[2];
  const float* Wk       = (const float*)d_in[3];
  const float* Wv       = (const float*)d_in[4];
  const float* gru_wi   = (const float*)d_in[5];
  const float* gru_wh   = (const float*)d_in[6];
  const float* gru_bi   = (const float*)d_in[7];
  const float* gru_bh   = (const float*)d_in[8];
  const float* ln_in_w  = (const float*)d_in[9];
  const float* ln_in_b  = (const float*)d_in[10];
  const float* ln_s_w   = (const float*)d_in[11];
  const float* ln_s_b   = (const float*)d_in[12];
  const float* ln_m_w   = (const float*)d_in[13];
  const float* ln_m_b   = (const float*)d_in[14];
  const float* mlp_w1   = (const float*)d_in[15];
  const float* mlp_b1   = (const float*)d_in[16];
  const float* mlp_w2   = (const float*)d_in[17];
  const float* mlp_b2   = (const float*)d_in[18];
  float* out = (float*)d_out;

  qprep0<<<NB, 384>>>(slotinit, out, Wq, Wk, ln_s_w, ln_s_b, ln_in_w, ln_in_b); // 1
  stats_k<<<(NB*NN)/8, 256>>>(inputs);                                          // 2
  dummy_k<<<1, 32>>>();                                                         // 3

  for (int it = 0; it < 3; it++){
    attn_scan<<<dim3(NB, NCH), 128>>>(inputs);   // 4th launch on it=0 (ncu)
    tail_bk<<<dim3(NB, 4), 256>>>(out, gru_wi, gru_wh, gru_bi, gru_bh,
                           ln_m_w, ln_m_b, mlp_w1, mlp_b1, mlp_w2, mlp_b2,
                           Wq, Wk, Wv, ln_s_w, ln_s_b, ln_in_w, ln_in_b,
                           (it < 2) ? 1 : 0);
  }
}

// round 16
// speedup vs baseline: 1.1582x; 1.1582x over previous
#include <cuda_runtime.h>
#include <cstdint>

// Problem constants
#define NB 64
#define NN 4096
#define NF 256
#define ND 128
#define NSLOT 8
#define NCH 32                  // block-chunks per batch (128 rows each)

// ---------------- device scratch ----------------
__device__ float g_part[(size_t)NB*NCH*NSLOT*NF];   // [b][c][k][f]
__device__ float g_t2p[NB*NCH*NSLOT];
__device__ float g_t3p[NB*NCH*NSLOT];
__device__ float g_c1[NB*NSLOT*NF];                 // lw * q'   [b][k][f]
__device__ float g_c2[NB*NSLOT];
__device__ float g_c3[NB*NSLOT];
__device__ float2 g_stats[(size_t)NB*NN];           // {mu, rs} per row

__device__ __forceinline__ float sigm(float x){ return 1.f / (1.f + expf(-x)); }

__global__ void dummy_k(){}

// =====================================================================
// stats_k: per-row LN stats, once. Warp per row.
// =====================================================================
__global__ void __launch_bounds__(256) stats_k(const float* __restrict__ X){
  const int warp = threadIdx.x >> 5, lane = threadIdx.x & 31;
  const size_t row = (size_t)blockIdx.x * 8 + warp;
  const float4* xr = (const float4*)(X + row*NF);
  float4 x0 = __ldg(xr + lane);
  float4 x1 = __ldg(xr + 32 + lane);
  float s  = ((x0.x + x0.y) + (x0.z + x0.w)) + ((x1.x + x1.y) + (x1.z + x1.w));
  float q2 = x0.x*x0.x;
  q2 = fmaf(x0.y, x0.y, q2); q2 = fmaf(x0.z, x0.z, q2); q2 = fmaf(x0.w, x0.w, q2);
  q2 = fmaf(x1.x, x1.x, q2); q2 = fmaf(x1.y, x1.y, q2);
  q2 = fmaf(x1.z, x1.z, q2); q2 = fmaf(x1.w, x1.w, q2);
  #pragma unroll
  for (int off = 16; off; off >>= 1){
    s  += __shfl_xor_sync(0xffffffffu, s,  off);
    q2 += __shfl_xor_sync(0xffffffffu, q2, off);
  }
  if (lane == 0){
    float mu = s * (1.f/256.f);
    float rs = rsqrtf(fmaf(q2, 1.f/256.f, -mu*mu) + 1e-5f);
    g_stats[row] = make_float2(mu, rs);
  }
}

// =====================================================================
// attn_scan v6 (best measured): c1 in smem, 2-row interleave, block combine.
// Grid (NB, 32), 128 threads (4 warps x 32 rows).
// =====================================================================
__global__ void __launch_bounds__(128, 3) attn_scan(const float* __restrict__ X){
  const int b = blockIdx.x, blk = blockIdx.y;
  const int tid = threadIdx.x;
  const int warp = tid >> 5, lane = tid & 31;

  __shared__ __align__(16) float s_c1[NSLOT*NF];      // 8KB
  __shared__ __align__(16) float s_buf[4][NSLOT*NF];  // 32KB
  __shared__ float s_t23[4][16];

  for (int i = tid; i < NSLOT*NF; i += 128) s_c1[i] = __ldg(g_c1 + b*NSLOT*NF + i);
  float c2[NSLOT], c3[NSLOT];
  #pragma unroll
  for (int k = 0; k < NSLOT; k++){
    c2[k] = __ldg(g_c2 + b*NSLOT + k);
    c3[k] = __ldg(g_c3 + b*NSLOT + k);
  }
  __syncthreads();

  float4 A0[NSLOT], A1[NSLOT];
  float t2a[NSLOT], t3a[NSLOT];
  #pragma unroll
  for (int k = 0; k < NSLOT; k++){
    A0[k] = make_float4(0.f,0.f,0.f,0.f);
    A1[k] = make_float4(0.f,0.f,0.f,0.f);
    t2a[k] = 0.f; t3a[k] = 0.f;
  }

  const size_t row0 = (size_t)b*NN + (size_t)blk*128 + (size_t)warp*32;
  const float* Xb = X + row0*NF;

  for (int r = 0; r < 32; r += 2){
    const float4* xr = (const float4*)(Xb + (size_t)r*NF);
    float4 x0 = __ldg(xr + lane);
    float4 x1 = __ldg(xr + 32 + lane);
    float4 y0 = __ldg(xr + 64 + lane);
    float4 y1 = __ldg(xr + 96 + lane);
    float2 stx = __ldg(&g_stats[row0 + r]);
    float2 sty = __ldg(&g_stats[row0 + r + 1]);

    float p[NSLOT], q[NSLOT];
    #pragma unroll
    for (int k = 0; k < NSLOT; k++){
      float4 ca = *(const float4*)(s_c1 + k*NF + lane*4);
      float4 cb = *(const float4*)(s_c1 + k*NF + 128 + lane*4);
      float pk = x0.x*ca.x;
      pk = fmaf(x0.y, ca.y, pk); pk = fmaf(x0.z, ca.z, pk); pk = fmaf(x0.w, ca.w, pk);
      pk = fmaf(x1.x, cb.x, pk); pk = fmaf(x1.y, cb.y, pk);
      pk = fmaf(x1.z, cb.z, pk); pk = fmaf(x1.w, cb.w, pk);
      p[k] = pk;
      float qk = y0.x*ca.x;
      qk = fmaf(y0.y, ca.y, qk); qk = fmaf(y0.z, ca.z, qk); qk = fmaf(y0.w, ca.w, qk);
      qk = fmaf(y1.x, cb.x, qk); qk = fmaf(y1.y, cb.y, qk);
      qk = fmaf(y1.z, cb.z, qk); qk = fmaf(y1.w, cb.w, qk);
      q[k] = qk;
    }
    #pragma unroll
    for (int off = 16; off; off >>= 1){
      #pragma unroll
      for (int k = 0; k < NSLOT; k++){
        p[k] += __shfl_xor_sync(0xffffffffu, p[k], off);
        q[k] += __shfl_xor_sync(0xffffffffu, q[k], off);
      }
    }

    {
      const float mu = stx.x, rs = stx.y;
      float lg[NSLOT];
      #pragma unroll
      for (int k = 0; k < NSLOT; k++)
        lg[k] = fmaf(rs, fmaf(-mu, c2[k], p[k]), c3[k]);
      float m = fmaxf(fmaxf(fmaxf(lg[0],lg[1]), fmaxf(lg[2],lg[3])),
                      fmaxf(fmaxf(lg[4],lg[5]), fmaxf(lg[6],lg[7])));
      float e[NSLOT], es = 0.f;
      #pragma unroll
      for (int k = 0; k < NSLOT; k++){ e[k] = __expf(lg[k] - m); es += e[k]; }
      float inv = __fdividef(1.f, es);
      #pragma unroll
      for (int k = 0; k < NSLOT; k++){
        float a  = fmaf(e[k], inv, 1e-8f);
        float ar = a * rs;
        t3a[k] += a;
        t2a[k] = fmaf(ar, mu, t2a[k]);
        A0[k].x = fmaf(ar, x0.x, A0[k].x);
        A0[k].y = fmaf(ar, x0.y, A0[k].y);
        A0[k].z = fmaf(ar, x0.z, A0[k].z);
        A0[k].w = fmaf(ar, x0.w, A0[k].w);
        A1[k].x = fmaf(ar, x1.x, A1[k].x);
        A1[k].y = fmaf(ar, x1.y, A1[k].y);
        A1[k].z = fmaf(ar, x1.z, A1[k].z);
        A1[k].w = fmaf(ar, x1.w, A1[k].w);
      }
    }
    {
      const float mu = sty.x, rs = sty.y;
      float lg[NSLOT];
      #pragma unroll
      for (int k = 0; k < NSLOT; k++)
        lg[k] = fmaf(rs, fmaf(-mu, c2[k], q[k]), c3[k]);
      float m = fmaxf(fmaxf(fmaxf(lg[0],lg[1]), fmaxf(lg[2],lg[3])),
                      fmaxf(fmaxf(lg[4],lg[5]), fmaxf(lg[6],lg[7])));
      float e[NSLOT], es = 0.f;
      #pragma unroll
      for (int k = 0; k < NSLOT; k++){ e[k] = __expf(lg[k] - m); es += e[k]; }
      float inv = __fdividef(1.f, es);
      #pragma unroll
      for (int k = 0; k < NSLOT; k++){
        float a  = fmaf(e[k], inv, 1e-8f);
        float ar = a * rs;
        t3a[k] += a;
        t2a[k] = fmaf(ar, mu, t2a[k]);
        A0[k].x = fmaf(ar, y0.x, A0[k].x);
        A0[k].y = fmaf(ar, y0.y, A0[k].y);
        A0[k].z = fmaf(ar, y0.z, A0[k].z);
        A0[k].w = fmaf(ar, y0.w, A0[k].w);
        A1[k].x = fmaf(ar, y1.x, A1[k].x);
        A1[k].y = fmaf(ar, y1.y, A1[k].y);
        A1[k].z = fmaf(ar, y1.z, A1[k].z);
        A1[k].w = fmaf(ar, y1.w, A1[k].w);
      }
    }
  }

  #pragma unroll
  for (int k = 0; k < NSLOT; k++){
    *(float4*)(s_buf[warp] + k*NF + lane*4)       = A0[k];
    *(float4*)(s_buf[warp] + k*NF + 128 + lane*4) = A1[k];
  }
  if (lane == 0){
    #pragma unroll
    for (int k = 0; k < NSLOT; k++){
      s_t23[warp][k]     = t2a[k];
      s_t23[warp][8 + k] = t3a[k];
    }
  }
  __syncthreads();

  float* gp = g_part + (size_t)((b*NCH + blk)*NSLOT)*NF;
  #pragma unroll
  for (int j = 0; j < 4; j++){
    int off = (tid + j*128) * 4;
    float4 v0 = *(const float4*)(s_buf[0] + off);
    float4 v1 = *(const float4*)(s_buf[1] + off);
    float4 v2 = *(const float4*)(s_buf[2] + off);
    float4 v3 = *(const float4*)(s_buf[3] + off);
    float4 v;
    v.x = (v0.x + v1.x) + (v2.x + v3.x);
    v.y = (v0.y + v1.y) + (v2.y + v3.y);
    v.z = (v0.z + v1.z) + (v2.z + v3.z);
    v.w = (v0.w + v1.w) + (v2.w + v3.w);
    *(float4*)(gp + off) = v;
  }
  if (tid < 16){
    float v = s_t23[0][tid] + s_t23[1][tid] + s_t23[2][tid] + s_t23[3][tid];
    if (tid < 8) g_t2p[(b*NCH + blk)*NSLOT + tid]       = v;
    else         g_t3p[(b*NCH + blk)*NSLOT + (tid - 8)] = v;
  }
}

// =====================================================================
// tail_bk v6: v5 + 1/t3 folded into s_wt (one fewer phase).
// Grid (NB, 4), 256 threads; slots kb, kb+1 with kb = blockIdx.y*2.
// =====================================================================
__global__ void __launch_bounds__(256) tail_bk(float* __restrict__ slots,
    const float* __restrict__ wi, const float* __restrict__ wh,
    const float* __restrict__ bi, const float* __restrict__ bh,
    const float* __restrict__ lnw, const float* __restrict__ lnb,   // ln_mlp
    const float* __restrict__ w1, const float* __restrict__ b1,
    const float* __restrict__ w2, const float* __restrict__ b2,
    const float* __restrict__ Wq, const float* __restrict__ Wk,
    const float* __restrict__ Wv,
    const float* __restrict__ lnqw, const float* __restrict__ lnqb, // ln_slots
    const float* __restrict__ liw, const float* __restrict__ lib,   // ln_in
    int do_q){
  const int b = blockIdx.x, kb = blockIdx.y*2, t = threadIdx.x;
  __shared__ float s_wt[2][256];
  __shared__ float s_sp[2][128], s_upd[2][128];
  __shared__ float s_gx[2][384], s_gh[2][384];
  __shared__ float s_mid[2][128], s_ln[2][128], s_h[2][256], s_new[2][128];
  __shared__ __align__(16) float s_q[2][128];
  __shared__ float s_qp[2][256];
  __shared__ float s_red[2][2][128];
  __shared__ float s_sc2[2], s_sc3[2], s_mu[2], s_rs[2];

  {
    int s = t >> 7, d = t & 127;
    s_sp[s][d] = slots[b*1024 + (kb+s)*128 + d];
  }

  // t2/t3 per slot: 4 warps -> (t2 s0, t2 s1, t3 s0, t3 s1)
  if (t < 128){
    int w = t >> 5, lane = t & 31;
    int s = w & 1;
    const float* src = (w < 2) ? g_t2p : g_t3p;
    float a = __ldg(src + (b*NCH + lane)*NSLOT + kb + s);
    #pragma unroll
    for (int off = 16; off; off >>= 1)
      a += __shfl_xor_sync(0xffffffffu, a, off);
    if (lane == 0){
      if (w < 2) s_sc2[s] = a; else s_sc3[s] = a;
    }
  }
  __syncthreads();

  // weighted[k][f] = (liw*(t1 - t2[k]) + lib*t3[k]) / t3[k]  (divide folded)
  for (int idx = t; idx < 512; idx += 256){
    int k = idx >> 8, f = idx & 255;
    const float* gp = g_part + ((size_t)(b*NCH)*NSLOT + kb + k)*NF + f;
    float acc = 0.f;
    #pragma unroll
    for (int cb = 0; cb < NCH; cb += 16){
      float v[16];
      #pragma unroll
      for (int j = 0; j < 16; j++) v[j] = __ldg(gp + (size_t)(cb+j)*NSLOT*NF);
      #pragma unroll
      for (int j = 0; j < 16; j++) acc += v[j];
    }
    float inv3 = __fdividef(1.f, s_sc3[k]);
    s_wt[k][f] = (liw[f]*(acc - s_sc2[k]) + lib[f]*s_sc3[k]) * inv3;
  }
  __syncthreads();

  // updates[k][d] = weighted @ Wv  (f in halves, 2 FMA per load)
  {
    int d = t & 127, h = t >> 7;
    float u0 = 0.f, u1 = 0.f;
    for (int fb = h*128; fb < h*128 + 128; fb += 16){
      float v[16];
      #pragma unroll
      for (int j = 0; j < 16; j++) v[j] = __ldg(Wv + (fb+j)*128 + d);
      #pragma unroll
      for (int j = 0; j < 16; j++){
        u0 = fmaf(s_wt[0][fb+j], v[j], u0);
        u1 = fmaf(s_wt[1][fb+j], v[j], u1);
      }
    }
    s_red[h][0][d] = u0; s_red[h][1][d] = u1;
  }
  __syncthreads();
  {
    int k = t >> 7, d = t & 127;
    s_upd[k][d] = s_red[0][k][d] + s_red[1][k][d];
  }
  __syncthreads();

  // GRU gates
  #pragma unroll
  for (int pass = 0; pass < 2; pass++){
    int g = pass ? (256 + t) : t;
    if (g < 384){
      float ax0 = bi[g], ah0 = bh[g];
      float ax1 = ax0, ah1 = ah0;
      for (int fb = 0; fb < 128; fb += 16){
        float a_[16], h_[16];
        #pragma unroll
        for (int j = 0; j < 16; j++){
          a_[j] = __ldg(wi + (fb+j)*384 + g);
          h_[j] = __ldg(wh + (fb+j)*384 + g);
        }
        #pragma unroll
        for (int j = 0; j < 16; j++){
          ax0 = fmaf(s_upd[0][fb+j], a_[j], ax0);
          ah0 = fmaf(s_sp[0][fb+j],  h_[j], ah0);
          ax1 = fmaf(s_upd[1][fb+j], a_[j], ax1);
          ah1 = fmaf(s_sp[1][fb+j],  h_[j], ah1);
        }
      }
      s_gx[0][g] = ax0; s_gh[0][g] = ah0;
      s_gx[1][g] = ax1; s_gh[1][g] = ah1;
    }
  }
  __syncthreads();

  {
    int k = t >> 7, d = t & 127;
    float r = sigm(s_gx[k][d] + s_gh[k][d]);
    float z = sigm(s_gx[k][128 + d] + s_gh[k][128 + d]);
    float n = tanhf(fmaf(r, s_gh[k][256 + d], s_gx[k][256 + d]));
    s_mid[k][d] = (1.f - z)*n + z*s_sp[k][d];
  }
  __syncthreads();

  // LN(mid): warp per slot
  if (t < 64){
    int s = t >> 5, lane = t & 31;
    float xs = 0.f, xq = 0.f;
    #pragma unroll
    for (int i = 0; i < 4; i++){
      float x = s_mid[s][lane + i*32];
      xs += x; xq = fmaf(x, x, xq);
    }
    #pragma unroll
    for (int off = 16; off; off >>= 1){
      xs += __shfl_xor_sync(0xffffffffu, xs, off);
      xq += __shfl_xor_sync(0xffffffffu, xq, off);
    }
    if (lane == 0){
      float mu = xs * (1.f/128.f);
      s_mu[s] = mu; s_rs[s] = rsqrtf(xq*(1.f/128.f) - mu*mu + 1e-5f);
    }
  }
  __syncthreads();
  {
    int k = t >> 7, d = t & 127;
    s_ln[k][d] = (s_mid[k][d] - s_mu[k])*s_rs[k]*lnw[d] + lnb[d];
  }
  __syncthreads();

  // hidden[k][c] = relu(ln @ w1 + b1)
  {
    int c = t;
    float h0 = b1[c], h1 = h0;
    for (int fb = 0; fb < 128; fb += 16){
      float v[16];
      #pragma unroll
      for (int j = 0; j < 16; j++) v[j] = __ldg(w1 + (fb+j)*256 + c);
      #pragma unroll
      for (int j = 0; j < 16; j++){
        h0 = fmaf(s_ln[0][fb+j], v[j], h0);
        h1 = fmaf(s_ln[1][fb+j], v[j], h1);
      }
    }
    s_h[0][c] = fmaxf(h0, 0.f); s_h[1][c] = fmaxf(h1, 0.f);
  }
  __syncthreads();

  // out[k][d] = mid + hidden @ w2 + b2
  {
    int d = t & 127, h = t >> 7;
    float o0 = 0.f, o1 = 0.f;
    for (int cb = h*128; cb < h*128 + 128; cb += 16){
      float v[16];
      #pragma unroll
      for (int j = 0; j < 16; j++) v[j] = __ldg(w2 + (cb+j)*128 + d);
      #pragma unroll
      for (int j = 0; j < 16; j++){
        o0 = fmaf(s_h[0][cb+j], v[j], o0);
        o1 = fmaf(s_h[1][cb+j], v[j], o1);
      }
    }
    s_red[h][0][d] = o0; s_red[h][1][d] = o1;
  }
  __syncthreads();
  {
    int k = t >> 7, d = t & 127;
    float o = s_mid[k][d] + b2[d] + s_red[0][k][d] + s_red[1][k][d];
    slots[b*1024 + (kb+k)*128 + d] = o;
    s_new[k][d] = o;
  }
  if (!do_q) return;
  __syncthreads();

  // LN(new) with ln_slots
  if (t < 64){
    int s = t >> 5, lane = t & 31;
    float xs = 0.f, xq = 0.f;
    #pragma unroll
    for (int i = 0; i < 4; i++){
      float x = s_new[s][lane + i*32];
      xs += x; xq = fmaf(x, x, xq);
    }
    #pragma unroll
    for (int off = 16; off; off >>= 1){
      xs += __shfl_xor_sync(0xffffffffu, xs, off);
      xq += __shfl_xor_sync(0xffffffffu, xq, off);
    }
    if (lane == 0){
      float mu = xs * (1.f/128.f);
      s_mu[s] = mu; s_rs[s] = rsqrtf(xq*(1.f/128.f) - mu*mu + 1e-5f);
    }
  }
  __syncthreads();
  {
    int k = t >> 7, d = t & 127;
    s_ln[k][d] = (s_new[k][d] - s_mu[k])*s_rs[k]*lnqw[d] + lnqb[d];
  }
  __syncthreads();

  // q[k][d] = (lnq @ Wq) * 1/sqrt(D)  (f in halves)
  {
    int d = t & 127, h = t >> 7;
    float a0 = 0.f, a1 = 0.f;
    for (int fb = h*64; fb < h*64 + 64; fb += 16){
      float v[16];
      #pragma unroll
      for (int j = 0; j < 16; j++) v[j] = __ldg(Wq + (fb+j)*128 + d);
      #pragma unroll
      for (int j = 0; j < 16; j++){
        a0 = fmaf(s_ln[0][fb+j], v[j], a0);
        a1 = fmaf(s_ln[1][fb+j], v[j], a1);
      }
    }
    s_red[h][0][d] = a0; s_red[h][1][d] = a1;
  }
  __syncthreads();
  {
    int k = t >> 7, d = t & 127;
    s_q[k][d] = (s_red[0][k][d] + s_red[1][k][d]) * 0.08838834764831845f;
  }
  __syncthreads();

  // q'[k][f] = Wk[f,:] . q[k]  (warp per 32 f, 8-value interleaved butterflies)
  {
    int w = t >> 5, lane = t & 31;
    float4 qv0 = *((const float4*)s_q[0] + lane);
    float4 qv1 = *((const float4*)s_q[1] + lane);
    for (int i = 0; i < 32; i += 4){
      float pp[8];
      #pragma unroll
      for (int j = 0; j < 4; j++){
        int f = w*32 + i + j;
        float4 wk = __ldg((const float4*)(Wk + f*128) + lane);
        float v0 = wk.x*qv0.x;
        v0 = fmaf(wk.y, qv0.y, v0);
        v0 = fmaf(wk.z, qv0.z, v0);
        v0 = fmaf(wk.w, qv0.w, v0);
        pp[j] = v0;
        float v1 = wk.x*qv1.x;
        v1 = fmaf(wk.y, qv1.y, v1);
        v1 = fmaf(wk.z, qv1.z, v1);
        v1 = fmaf(wk.w, qv1.w, v1);
        pp[4+j] = v1;
      }
      #pragma unroll
      for (int off = 16; off; off >>= 1)
        #pragma unroll
        for (int j = 0; j < 8; j++)
          pp[j] += __shfl_xor_sync(0xffffffffu, pp[j], off);
      if (lane == 0){
        #pragma unroll
        for (int j = 0; j < 4; j++){
          int f = w*32 + i + j;
          s_qp[0][f] = pp[j];
          s_qp[1][f] = pp[4+j];
          g_c1[b*2048 + kb*256 + f]       = liw[f] * pp[j];
          g_c1[b*2048 + (kb+1)*256 + f]   = liw[f] * pp[4+j];
        }
      }
    }
  }
  __syncthreads();

  // c2/c3 per slot (warp per slot)
  if (t < 64){
    int s = t >> 5, lane = t & 31;
    float a2 = 0.f, a3 = 0.f;
    #pragma unroll
    for (int i = 0; i < 8; i++){
      int f = lane + i*32;
      a2 = fmaf(liw[f], s_qp[s][f], a2);
      a3 = fmaf(lib[f], s_qp[s][f], a3);
    }
    #pragma unroll
    for (int off = 16; off; off >>= 1){
      a2 += __shfl_xor_sync(0xffffffffu, a2, off);
      a3 += __shfl_xor_sync(0xffffffffu, a3, off);
    }
    if (lane == 0){
      g_c2[b*NSLOT + kb + s] = a2;
      g_c3[b*NSLOT + kb + s] = a3;
    }
  }
}

// =====================================================================
// qprep0: init slots + first-iteration c1/c2/c3 (batched loads)
// =====================================================================
__global__ void __launch_bounds__(384) qprep0(const float* __restrict__ si,
    float* __restrict__ slots,
    const float* __restrict__ Wq, const float* __restrict__ Wk,
    const float* __restrict__ lnqw, const float* __restrict__ lnqb,
    const float* __restrict__ liw, const float* __restrict__ lib){
  const int b = blockIdx.x, t = threadIdx.x;
  __shared__ float s_new[1024], s_lnq[1024], s_q[1024], s_qp[2048];
  __shared__ float smu[NSLOT], srs[NSLOT];
  for (int idx = t; idx < 1024; idx += 384){
    float v = si[idx];
    s_new[idx] = v;
    slots[b*1024 + idx] = v;
  }
  __syncthreads();
  if (t < NSLOT){
    float su = 0.f, sq = 0.f;
    for (int d = 0; d < ND; d++){ float x = s_new[t*ND + d]; su += x; sq = fmaf(x,x,sq); }
    float mu = su * (1.f/ND);
    smu[t] = mu; srs[t] = rsqrtf(sq*(1.f/ND) - mu*mu + 1e-5f);
  }
  __syncthreads();
  for (int idx = t; idx < 1024; idx += 384){
    int j = idx >> 7, d = idx & 127;
    s_lnq[idx] = (s_new[idx] - smu[j]) * srs[j] * lnqw[d] + lnqb[d];
  }
  __syncthreads();
  const float inv_scale = 0.08838834764831845f;
  for (int idx = t; idx < 1024; idx += 384){
    int j = idx >> 7, d = idx & 127;
    float a = 0.f;
    for (int fb = 0; fb < 128; fb += 8){
      float v[8];
      #pragma unroll
      for (int u = 0; u < 8; u++) v[u] = __ldg(Wq + (fb+u)*128 + d);
      #pragma unroll
      for (int u = 0; u < 8; u++) a = fmaf(s_lnq[j*128 + fb+u], v[u], a);
    }
    s_q[idx] = a * inv_scale;
  }
  __syncthreads();
  for (int idx = t; idx < 2048; idx += 384){
    int k = idx >> 8, f = idx & 255;
    float qp = 0.f;
    const float* qrow = s_q + k*128;
    const float* wrow = Wk + f*128;
    for (int fb = 0; fb < 128; fb += 8){
      float v[8];
      #pragma unroll
      for (int u = 0; u < 8; u++) v[u] = __ldg(wrow + fb + u);
      #pragma unroll
      for (int u = 0; u < 8; u++) qp = fmaf(qrow[fb+u], v[u], qp);
    }
    s_qp[idx] = qp;
    g_c1[b*2048 + idx] = liw[f] * qp;
  }
  __syncthreads();
  if (t < NSLOT){
    float a2 = 0.f, a3 = 0.f;
    for (int f = 0; f < 256; f++){
      a2 = fmaf(liw[f], s_qp[t*256 + f], a2);
      a3 = fmaf(lib[f], s_qp[t*256 + f], a3);
    }
    g_c2[b*NSLOT + t] = a2;
    g_c3[b*NSLOT + t] = a3;
  }
}

// ---------------- launch ----------------
extern "C" void kernel_launch(void* const* d_in, const int* in_sizes, int n_in,
                              void* d_out, int out_size){
  const float* inputs   = (const float*)d_in[0];
  const float* slotinit = (const float*)d_in[1];
  const float* Wq       = (const float*)d_in[2];
  const float* Wk       = (const float*)d_in[3];
  const float* Wv       = (const float*)d_in[4];
  const float* gru_wi   = (const float*)d_in[5];
  const float* gru_wh   = (const float*)d_in[6];
  const float* gru_bi   = (const float*)d_in[7];
  const float* gru_bh   = (const float*)d_in[8];
  const float* ln_in_w  = (const float*)d_in[9];
  const float* ln_in_b  = (const float*)d_in[10];
  const float* ln_s_w   = (const float*)d_in[11];
  const float* ln_s_b   = (const float*)d_in[12];
  const float* ln_m_w   = (const float*)d_in[13];
  const float* ln_m_b   = (const float*)d_in[14];
  const float* mlp_w1   = (const float*)d_in[15];
  const float* mlp_b1   = (const float*)d_in[16];
  const float* mlp_w2   = (const float*)d_in[17];
  const float* mlp_b2   = (const float*)d_in[18];
  float* out = (float*)d_out;

  qprep0<<<NB, 384>>>(slotinit, out, Wq, Wk, ln_s_w, ln_s_b, ln_in_w, ln_in_b); // 1
  stats_k<<<(NB*NN)/8, 256>>>(inputs);                                          // 2
  dummy_k<<<1, 32>>>();                                                         // 3

  for (int it = 0; it < 3; it++){
    attn_scan<<<dim3(NB, NCH), 128>>>(inputs);   // 4th launch on it=0 (ncu clock canary)
    tail_bk<<<dim3(NB, 4), 256>>>(out, gru_wi, gru_wh, gru_bi, gru_bh,
                           ln_m_w, ln_m_b, mlp_w1, mlp_b1, mlp_w2, mlp_b2,
                           Wq, Wk, Wv, ln_s_w, ln_s_b, ln_in_w, ln_in_b,
                           (it < 2) ? 1 : 0);
  }
}

// round 17
// speedup vs baseline: 1.2585x; 1.0865x over previous
#include <cuda_runtime.h>
#include <cstdint>

// Problem constants
#define NB 64
#define NN 4096
#define NF 256
#define ND 128
#define NSLOT 8
#define NCH 32                  // block-chunks per batch (128 rows each)

// ---------------- device scratch ----------------
__device__ float g_part[(size_t)NB*NCH*NSLOT*NF];   // [b][c][k][f]
__device__ float g_t2p[NB*NCH*NSLOT];
__device__ float g_t3p[NB*NCH*NSLOT];
__device__ float g_c1[NB*NSLOT*NF];                 // lw * q'   [b][k][f]
__device__ float g_c2[NB*NSLOT];
__device__ float g_c3[NB*NSLOT];
__device__ float2 g_stats[(size_t)NB*NN];           // {mu, rs} per row

__device__ __forceinline__ float sigm(float x){ return 1.f / (1.f + expf(-x)); }

__global__ void dummy_k(){}

// =====================================================================
// stats_k: per-row LN stats, once. Warp per row.
// =====================================================================
__global__ void __launch_bounds__(256) stats_k(const float* __restrict__ X){
  const int warp = threadIdx.x >> 5, lane = threadIdx.x & 31;
  const size_t row = (size_t)blockIdx.x * 8 + warp;
  const float4* xr = (const float4*)(X + row*NF);
  float4 x0 = __ldg(xr + lane);
  float4 x1 = __ldg(xr + 32 + lane);
  float s  = ((x0.x + x0.y) + (x0.z + x0.w)) + ((x1.x + x1.y) + (x1.z + x1.w));
  float q2 = x0.x*x0.x;
  q2 = fmaf(x0.y, x0.y, q2); q2 = fmaf(x0.z, x0.z, q2); q2 = fmaf(x0.w, x0.w, q2);
  q2 = fmaf(x1.x, x1.x, q2); q2 = fmaf(x1.y, x1.y, q2);
  q2 = fmaf(x1.z, x1.z, q2); q2 = fmaf(x1.w, x1.w, q2);
  #pragma unroll
  for (int off = 16; off; off >>= 1){
    s  += __shfl_xor_sync(0xffffffffu, s,  off);
    q2 += __shfl_xor_sync(0xffffffffu, q2, off);
  }
  if (lane == 0){
    float mu = s * (1.f/256.f);
    float rs = rsqrtf(fmaf(q2, 1.f/256.f, -mu*mu) + 1e-5f);
    g_stats[row] = make_float2(mu, rs);
  }
}

// =====================================================================
// attn_scan v9: fold-and-merge reduce + lane-owned softmax.
// Lane l owns slot k = (l>>2)&7 after the merge-reduce; one exp per lane.
// Grid (NB, 32), 128 threads (4 warps x 32 rows).
// =====================================================================
__global__ void __launch_bounds__(128, 3) attn_scan(const float* __restrict__ X){
  const int b = blockIdx.x, blk = blockIdx.y;
  const int tid = threadIdx.x;
  const int warp = tid >> 5, lane = tid & 31;
  const int klane = (lane >> 2) & 7;

  __shared__ __align__(16) float s_c1[NSLOT*NF];      // 8KB
  __shared__ __align__(16) float s_buf[4][NSLOT*NF];  // 32KB
  __shared__ float s_t23[4][16];

  for (int i = tid; i < NSLOT*NF; i += 128) s_c1[i] = __ldg(g_c1 + b*NSLOT*NF + i);
  const float c2k = __ldg(g_c2 + b*NSLOT + klane);
  const float c3k = __ldg(g_c3 + b*NSLOT + klane);
  __syncthreads();

  float4 A0[NSLOT], A1[NSLOT];
  float t2own = 0.f, t3own = 0.f;
  #pragma unroll
  for (int k = 0; k < NSLOT; k++){
    A0[k] = make_float4(0.f,0.f,0.f,0.f);
    A1[k] = make_float4(0.f,0.f,0.f,0.f);
  }

  const size_t row0 = (size_t)b*NN + (size_t)blk*128 + (size_t)warp*32;
  const float* Xb = X + row0*NF;
  const bool b16 = (lane & 16) != 0;
  const bool b8  = (lane & 8)  != 0;
  const bool b4  = (lane & 4)  != 0;

  for (int r = 0; r < 32; r += 2){
    const float4* xr = (const float4*)(Xb + (size_t)r*NF);
    float4 x0 = __ldg(xr + lane);
    float4 x1 = __ldg(xr + 32 + lane);
    float4 y0 = __ldg(xr + 64 + lane);
    float4 y1 = __ldg(xr + 96 + lane);
    float2 stx = __ldg(&g_stats[row0 + r]);
    float2 sty = __ldg(&g_stats[row0 + r + 1]);

    // dot partials
    float p[NSLOT], q[NSLOT];
    #pragma unroll
    for (int k = 0; k < NSLOT; k++){
      float4 ca = *(const float4*)(s_c1 + k*NF + lane*4);
      float4 cb = *(const float4*)(s_c1 + k*NF + 128 + lane*4);
      float pk = x0.x*ca.x;
      pk = fmaf(x0.y, ca.y, pk); pk = fmaf(x0.z, ca.z, pk); pk = fmaf(x0.w, ca.w, pk);
      pk = fmaf(x1.x, cb.x, pk); pk = fmaf(x1.y, cb.y, pk);
      pk = fmaf(x1.z, cb.z, pk); pk = fmaf(x1.w, cb.w, pk);
      p[k] = pk;
      float qk = y0.x*ca.x;
      qk = fmaf(y0.y, ca.y, qk); qk = fmaf(y0.z, ca.z, qk); qk = fmaf(y0.w, ca.w, qk);
      qk = fmaf(y1.x, cb.x, qk); qk = fmaf(y1.y, cb.y, qk);
      qk = fmaf(y1.z, cb.z, qk); qk = fmaf(y1.w, cb.w, qk);
      q[k] = qk;
    }

    // fold-and-merge reduce: lane ends with full dot for its k=(lane>>2)&7
    #pragma unroll
    for (int k = 0; k < NSLOT; k++){
      p[k] += __shfl_xor_sync(0xffffffffu, p[k], 16);
      q[k] += __shfl_xor_sync(0xffffffffu, q[k], 16);
    }
    float pr[4], qr[4];
    #pragma unroll
    for (int j = 0; j < 4; j++){
      pr[j] = b16 ? p[j+4] : p[j];
      qr[j] = b16 ? q[j+4] : q[j];
    }
    #pragma unroll
    for (int j = 0; j < 4; j++){
      pr[j] += __shfl_xor_sync(0xffffffffu, pr[j], 8);
      qr[j] += __shfl_xor_sync(0xffffffffu, qr[j], 8);
    }
    float ps0 = b8 ? pr[2] : pr[0];
    float ps1 = b8 ? pr[3] : pr[1];
    float qs0 = b8 ? qr[2] : qr[0];
    float qs1 = b8 ? qr[3] : qr[1];
    ps0 += __shfl_xor_sync(0xffffffffu, ps0, 4);
    ps1 += __shfl_xor_sync(0xffffffffu, ps1, 4);
    qs0 += __shfl_xor_sync(0xffffffffu, qs0, 4);
    qs1 += __shfl_xor_sync(0xffffffffu, qs1, 4);
    float pu = b4 ? ps1 : ps0;
    float qu = b4 ? qs1 : qs0;
    pu += __shfl_xor_sync(0xffffffffu, pu, 2);
    qu += __shfl_xor_sync(0xffffffffu, qu, 2);
    pu += __shfl_xor_sync(0xffffffffu, pu, 1);
    qu += __shfl_xor_sync(0xffffffffu, qu, 1);

    // lane-owned softmax (row r and r+1 interleaved)
    float lgp = fmaf(stx.y, fmaf(-stx.x, c2k, pu), c3k);
    float lgq = fmaf(sty.y, fmaf(-sty.x, c2k, qu), c3k);
    float mp = lgp, mq = lgq;
    mp = fmaxf(mp, __shfl_xor_sync(0xffffffffu, mp, 16));
    mq = fmaxf(mq, __shfl_xor_sync(0xffffffffu, mq, 16));
    mp = fmaxf(mp, __shfl_xor_sync(0xffffffffu, mp, 8));
    mq = fmaxf(mq, __shfl_xor_sync(0xffffffffu, mq, 8));
    mp = fmaxf(mp, __shfl_xor_sync(0xffffffffu, mp, 4));
    mq = fmaxf(mq, __shfl_xor_sync(0xffffffffu, mq, 4));
    float ep = __expf(lgp - mp);
    float eq = __expf(lgq - mq);
    float esp = ep, esq = eq;
    esp += __shfl_xor_sync(0xffffffffu, esp, 16);
    esq += __shfl_xor_sync(0xffffffffu, esq, 16);
    esp += __shfl_xor_sync(0xffffffffu, esp, 8);
    esq += __shfl_xor_sync(0xffffffffu, esq, 8);
    esp += __shfl_xor_sync(0xffffffffu, esp, 4);
    esq += __shfl_xor_sync(0xffffffffu, esq, 4);
    float ap = fmaf(ep, __fdividef(1.f, esp), 1e-8f);
    float aq = fmaf(eq, __fdividef(1.f, esq), 1e-8f);
    float arp_own = ap * stx.y;
    float arq_own = aq * sty.y;
    t3own += ap + aq;
    t2own = fmaf(arp_own, stx.x, t2own);
    t2own = fmaf(arq_own, sty.x, t2own);

    // broadcast ar to all lanes (source lane k*4)
    float arp[NSLOT], arq[NSLOT];
    #pragma unroll
    for (int k = 0; k < NSLOT; k++){
      arp[k] = __shfl_sync(0xffffffffu, arp_own, k << 2);
      arq[k] = __shfl_sync(0xffffffffu, arq_own, k << 2);
    }

    // rank-8 accumulate (both rows)
    #pragma unroll
    for (int k = 0; k < NSLOT; k++){
      float a0 = arp[k], a1 = arq[k];
      A0[k].x = fmaf(a0, x0.x, A0[k].x);
      A0[k].y = fmaf(a0, x0.y, A0[k].y);
      A0[k].z = fmaf(a0, x0.z, A0[k].z);
      A0[k].w = fmaf(a0, x0.w, A0[k].w);
      A1[k].x = fmaf(a0, x1.x, A1[k].x);
      A1[k].y = fmaf(a0, x1.y, A1[k].y);
      A1[k].z = fmaf(a0, x1.z, A1[k].z);
      A1[k].w = fmaf(a0, x1.w, A1[k].w);
      A0[k].x = fmaf(a1, y0.x, A0[k].x);
      A0[k].y = fmaf(a1, y0.y, A0[k].y);
      A0[k].z = fmaf(a1, y0.z, A0[k].z);
      A0[k].w = fmaf(a1, y0.w, A0[k].w);
      A1[k].x = fmaf(a1, y1.x, A1[k].x);
      A1[k].y = fmaf(a1, y1.y, A1[k].y);
      A1[k].z = fmaf(a1, y1.z, A1[k].z);
      A1[k].w = fmaf(a1, y1.w, A1[k].w);
    }
  }

  // block combine
  #pragma unroll
  for (int k = 0; k < NSLOT; k++){
    *(float4*)(s_buf[warp] + k*NF + lane*4)       = A0[k];
    *(float4*)(s_buf[warp] + k*NF + 128 + lane*4) = A1[k];
  }
  if ((lane & 3) == 0){
    s_t23[warp][klane]     = t2own;
    s_t23[warp][8 + klane] = t3own;
  }
  __syncthreads();

  float* gp = g_part + (size_t)((b*NCH + blk)*NSLOT)*NF;
  #pragma unroll
  for (int j = 0; j < 4; j++){
    int off = (tid + j*128) * 4;
    float4 v0 = *(const float4*)(s_buf[0] + off);
    float4 v1 = *(const float4*)(s_buf[1] + off);
    float4 v2 = *(const float4*)(s_buf[2] + off);
    float4 v3 = *(const float4*)(s_buf[3] + off);
    float4 v;
    v.x = (v0.x + v1.x) + (v2.x + v3.x);
    v.y = (v0.y + v1.y) + (v2.y + v3.y);
    v.z = (v0.z + v1.z) + (v2.z + v3.z);
    v.w = (v0.w + v1.w) + (v2.w + v3.w);
    *(float4*)(gp + off) = v;
  }
  if (tid < 16){
    float v = s_t23[0][tid] + s_t23[1][tid] + s_t23[2][tid] + s_t23[3][tid];
    if (tid < 8) g_t2p[(b*NCH + blk)*NSLOT + tid]       = v;
    else         g_t3p[(b*NCH + blk)*NSLOT + (tid - 8)] = v;
  }
}

// =====================================================================
// tail_bk v6: 2 slots per block, 1/t3 folded. Grid (NB, 4), 256 thr.
// =====================================================================
__global__ void __launch_bounds__(256) tail_bk(float* __restrict__ slots,
    const float* __restrict__ wi, const float* __restrict__ wh,
    const float* __restrict__ bi, const float* __restrict__ bh,
    const float* __restrict__ lnw, const float* __restrict__ lnb,   // ln_mlp
    const float* __restrict__ w1, const float* __restrict__ b1,
    const float* __restrict__ w2, const float* __restrict__ b2,
    const float* __restrict__ Wq, const float* __restrict__ Wk,
    const float* __restrict__ Wv,
    const float* __restrict__ lnqw, const float* __restrict__ lnqb, // ln_slots
    const float* __restrict__ liw, const float* __restrict__ lib,   // ln_in
    int do_q){
  const int b = blockIdx.x, kb = blockIdx.y*2, t = threadIdx.x;
  __shared__ float s_wt[2][256];
  __shared__ float s_sp[2][128], s_upd[2][128];
  __shared__ float s_gx[2][384], s_gh[2][384];
  __shared__ float s_mid[2][128], s_ln[2][128], s_h[2][256], s_new[2][128];
  __shared__ __align__(16) float s_q[2][128];
  __shared__ float s_qp[2][256];
  __shared__ float s_red[2][2][128];
  __shared__ float s_sc2[2], s_sc3[2], s_mu[2], s_rs[2];

  {
    int s = t >> 7, d = t & 127;
    s_sp[s][d] = slots[b*1024 + (kb+s)*128 + d];
  }

  if (t < 128){
    int w = t >> 5, lane = t & 31;
    int s = w & 1;
    const float* src = (w < 2) ? g_t2p : g_t3p;
    float a = __ldg(src + (b*NCH + lane)*NSLOT + kb + s);
    #pragma unroll
    for (int off = 16; off; off >>= 1)
      a += __shfl_xor_sync(0xffffffffu, a, off);
    if (lane == 0){
      if (w < 2) s_sc2[s] = a; else s_sc3[s] = a;
    }
  }
  __syncthreads();

  for (int idx = t; idx < 512; idx += 256){
    int k = idx >> 8, f = idx & 255;
    const float* gp = g_part + ((size_t)(b*NCH)*NSLOT + kb + k)*NF + f;
    float acc = 0.f;
    #pragma unroll
    for (int cb = 0; cb < NCH; cb += 16){
      float v[16];
      #pragma unroll
      for (int j = 0; j < 16; j++) v[j] = __ldg(gp + (size_t)(cb+j)*NSLOT*NF);
      #pragma unroll
      for (int j = 0; j < 16; j++) acc += v[j];
    }
    float inv3 = __fdividef(1.f, s_sc3[k]);
    s_wt[k][f] = (liw[f]*(acc - s_sc2[k]) + lib[f]*s_sc3[k]) * inv3;
  }
  __syncthreads();

  {
    int d = t & 127, h = t >> 7;
    float u0 = 0.f, u1 = 0.f;
    for (int fb = h*128; fb < h*128 + 128; fb += 16){
      float v[16];
      #pragma unroll
      for (int j = 0; j < 16; j++) v[j] = __ldg(Wv + (fb+j)*128 + d);
      #pragma unroll
      for (int j = 0; j < 16; j++){
        u0 = fmaf(s_wt[0][fb+j], v[j], u0);
        u1 = fmaf(s_wt[1][fb+j], v[j], u1);
      }
    }
    s_red[h][0][d] = u0; s_red[h][1][d] = u1;
  }
  __syncthreads();
  {
    int k = t >> 7, d = t & 127;
    s_upd[k][d] = s_red[0][k][d] + s_red[1][k][d];
  }
  __syncthreads();

  #pragma unroll
  for (int pass = 0; pass < 2; pass++){
    int g = pass ? (256 + t) : t;
    if (g < 384){
      float ax0 = bi[g], ah0 = bh[g];
      float ax1 = ax0, ah1 = ah0;
      for (int fb = 0; fb < 128; fb += 16){
        float a_[16], h_[16];
        #pragma unroll
        for (int j = 0; j < 16; j++){
          a_[j] = __ldg(wi + (fb+j)*384 + g);
          h_[j] = __ldg(wh + (fb+j)*384 + g);
        }
        #pragma unroll
        for (int j = 0; j < 16; j++){
          ax0 = fmaf(s_upd[0][fb+j], a_[j], ax0);
          ah0 = fmaf(s_sp[0][fb+j],  h_[j], ah0);
          ax1 = fmaf(s_upd[1][fb+j], a_[j], ax1);
          ah1 = fmaf(s_sp[1][fb+j],  h_[j], ah1);
        }
      }
      s_gx[0][g] = ax0; s_gh[0][g] = ah0;
      s_gx[1][g] = ax1; s_gh[1][g] = ah1;
    }
  }
  __syncthreads();

  {
    int k = t >> 7, d = t & 127;
    float r = sigm(s_gx[k][d] + s_gh[k][d]);
    float z = sigm(s_gx[k][128 + d] + s_gh[k][128 + d]);
    float n = tanhf(fmaf(r, s_gh[k][256 + d], s_gx[k][256 + d]));
    s_mid[k][d] = (1.f - z)*n + z*s_sp[k][d];
  }
  __syncthreads();

  if (t < 64){
    int s = t >> 5, lane = t & 31;
    float xs = 0.f, xq = 0.f;
    #pragma unroll
    for (int i = 0; i < 4; i++){
      float x = s_mid[s][lane + i*32];
      xs += x; xq = fmaf(x, x, xq);
    }
    #pragma unroll
    for (int off = 16; off; off >>= 1){
      xs += __shfl_xor_sync(0xffffffffu, xs, off);
      xq += __shfl_xor_sync(0xffffffffu, xq, off);
    }
    if (lane == 0){
      float mu = xs * (1.f/128.f);
      s_mu[s] = mu; s_rs[s] = rsqrtf(xq*(1.f/128.f) - mu*mu + 1e-5f);
    }
  }
  __syncthreads();
  {
    int k = t >> 7, d = t & 127;
    s_ln[k][d] = (s_mid[k][d] - s_mu[k])*s_rs[k]*lnw[d] + lnb[d];
  }
  __syncthreads();

  {
    int c = t;
    float h0 = b1[c], h1 = h0;
    for (int fb = 0; fb < 128; fb += 16){
      float v[16];
      #pragma unroll
      for (int j = 0; j < 16; j++) v[j] = __ldg(w1 + (fb+j)*256 + c);
      #pragma unroll
      for (int j = 0; j < 16; j++){
        h0 = fmaf(s_ln[0][fb+j], v[j], h0);
        h1 = fmaf(s_ln[1][fb+j], v[j], h1);
      }
    }
    s_h[0][c] = fmaxf(h0, 0.f); s_h[1][c] = fmaxf(h1, 0.f);
  }
  __syncthreads();

  {
    int d = t & 127, h = t >> 7;
    float o0 = 0.f, o1 = 0.f;
    for (int cb = h*128; cb < h*128 + 128; cb += 16){
      float v[16];
      #pragma unroll
      for (int j = 0; j < 16; j++) v[j] = __ldg(w2 + (cb+j)*128 + d);
      #pragma unroll
      for (int j = 0; j < 16; j++){
        o0 = fmaf(s_h[0][cb+j], v[j], o0);
        o1 = fmaf(s_h[1][cb+j], v[j], o1);
      }
    }
    s_red[h][0][d] = o0; s_red[h][1][d] = o1;
  }
  __syncthreads();
  {
    int k = t >> 7, d = t & 127;
    float o = s_mid[k][d] + b2[d] + s_red[0][k][d] + s_red[1][k][d];
    slots[b*1024 + (kb+k)*128 + d] = o;
    s_new[k][d] = o;
  }
  if (!do_q) return;
  __syncthreads();

  if (t < 64){
    int s = t >> 5, lane = t & 31;
    float xs = 0.f, xq = 0.f;
    #pragma unroll
    for (int i = 0; i < 4; i++){
      float x = s_new[s][lane + i*32];
      xs += x; xq = fmaf(x, x, xq);
    }
    #pragma unroll
    for (int off = 16; off; off >>= 1){
      xs += __shfl_xor_sync(0xffffffffu, xs, off);
      xq += __shfl_xor_sync(0xffffffffu, xq, off);
    }
    if (lane == 0){
      float mu = xs * (1.f/128.f);
      s_mu[s] = mu; s_rs[s] = rsqrtf(xq*(1.f/128.f) - mu*mu + 1e-5f);
    }
  }
  __syncthreads();
  {
    int k = t >> 7, d = t & 127;
    s_ln[k][d] = (s_new[k][d] - s_mu[k])*s_rs[k]*lnqw[d] + lnqb[d];
  }
  __syncthreads();

  {
    int d = t & 127, h = t >> 7;
    float a0 = 0.f, a1 = 0.f;
    for (int fb = h*64; fb < h*64 + 64; fb += 16){
      float v[16];
      #pragma unroll
      for (int j = 0; j < 16; j++) v[j] = __ldg(Wq + (fb+j)*128 + d);
      #pragma unroll
      for (int j = 0; j < 16; j++){
        a0 = fmaf(s_ln[0][fb+j], v[j], a0);
        a1 = fmaf(s_ln[1][fb+j], v[j], a1);
      }
    }
    s_red[h][0][d] = a0; s_red[h][1][d] = a1;
  }
  __syncthreads();
  {
    int k = t >> 7, d = t & 127;
    s_q[k][d] = (s_red[0][k][d] + s_red[1][k][d]) * 0.08838834764831845f;
  }
  __syncthreads();

  {
    int w = t >> 5, lane = t & 31;
    float4 qv0 = *((const float4*)s_q[0] + lane);
    float4 qv1 = *((const float4*)s_q[1] + lane);
    for (int i = 0; i < 32; i += 4){
      float pp[8];
      #pragma unroll
      for (int j = 0; j < 4; j++){
        int f = w*32 + i + j;
        float4 wk = __ldg((const float4*)(Wk + f*128) + lane);
        float v0 = wk.x*qv0.x;
        v0 = fmaf(wk.y, qv0.y, v0);
        v0 = fmaf(wk.z, qv0.z, v0);
        v0 = fmaf(wk.w, qv0.w, v0);
        pp[j] = v0;
        float v1 = wk.x*qv1.x;
        v1 = fmaf(wk.y, qv1.y, v1);
        v1 = fmaf(wk.z, qv1.z, v1);
        v1 = fmaf(wk.w, qv1.w, v1);
        pp[4+j] = v1;
      }
      #pragma unroll
      for (int off = 16; off; off >>= 1)
        #pragma unroll
        for (int j = 0; j < 8; j++)
          pp[j] += __shfl_xor_sync(0xffffffffu, pp[j], off);
      if (lane == 0){
        #pragma unroll
        for (int j = 0; j < 4; j++){
          int f = w*32 + i + j;
          s_qp[0][f] = pp[j];
          s_qp[1][f] = pp[4+j];
          g_c1[b*2048 + kb*256 + f]       = liw[f] * pp[j];
          g_c1[b*2048 + (kb+1)*256 + f]   = liw[f] * pp[4+j];
        }
      }
    }
  }
  __syncthreads();

  if (t < 64){
    int s = t >> 5, lane = t & 31;
    float a2 = 0.f, a3 = 0.f;
    #pragma unroll
    for (int i = 0; i < 8; i++){
      int f = lane + i*32;
      a2 = fmaf(liw[f], s_qp[s][f], a2);
      a3 = fmaf(lib[f], s_qp[s][f], a3);
    }
    #pragma unroll
    for (int off = 16; off; off >>= 1){
      a2 += __shfl_xor_sync(0xffffffffu, a2, off);
      a3 += __shfl_xor_sync(0xffffffffu, a3, off);
    }
    if (lane == 0){
      g_c2[b*NSLOT + kb + s] = a2;
      g_c3[b*NSLOT + kb + s] = a3;
    }
  }
}

// =====================================================================
// qprep0: init slots + first-iteration c1/c2/c3 (batched loads)
// =====================================================================
__global__ void __launch_bounds__(384) qprep0(const float* __restrict__ si,
    float* __restrict__ slots,
    const float* __restrict__ Wq, const float* __restrict__ Wk,
    const float* __restrict__ lnqw, const float* __restrict__ lnqb,
    const float* __restrict__ liw, const float* __restrict__ lib){
  const int b = blockIdx.x, t = threadIdx.x;
  __shared__ float s_new[1024], s_lnq[1024], s_q[1024], s_qp[2048];
  __shared__ float smu[NSLOT], srs[NSLOT];
  for (int idx = t; idx < 1024; idx += 384){
    float v = si[idx];
    s_new[idx] = v;
    slots[b*1024 + idx] = v;
  }
  __syncthreads();
  if (t < NSLOT){
    float su = 0.f, sq = 0.f;
    for (int d = 0; d < ND; d++){ float x = s_new[t*ND + d]; su += x; sq = fmaf(x,x,sq); }
    float mu = su * (1.f/ND);
    smu[t] = mu; srs[t] = rsqrtf(sq*(1.f/ND) - mu*mu + 1e-5f);
  }
  __syncthreads();
  for (int idx = t; idx < 1024; idx += 384){
    int j = idx >> 7, d = idx & 127;
    s_lnq[idx] = (s_new[idx] - smu[j]) * srs[j] * lnqw[d] + lnqb[d];
  }
  __syncthreads();
  const float inv_scale = 0.08838834764831845f;
  for (int idx = t; idx < 1024; idx += 384){
    int j = idx >> 7, d = idx & 127;
    float a = 0.f;
    for (int fb = 0; fb < 128; fb += 8){
      float v[8];
      #pragma unroll
      for (int u = 0; u < 8; u++) v[u] = __ldg(Wq + (fb+u)*128 + d);
      #pragma unroll
      for (int u = 0; u < 8; u++) a = fmaf(s_lnq[j*128 + fb+u], v[u], a);
    }
    s_q[idx] = a * inv_scale;
  }
  __syncthreads();
  for (int idx = t; idx < 2048; idx += 384){
    int k = idx >> 8, f = idx & 255;
    float qp = 0.f;
    const float* qrow = s_q + k*128;
    const float* wrow = Wk + f*128;
    for (int fb = 0; fb < 128; fb += 8){
      float v[8];
      #pragma unroll
      for (int u = 0; u < 8; u++) v[u] = __ldg(wrow + fb + u);
      #pragma unroll
      for (int u = 0; u < 8; u++) qp = fmaf(qrow[fb+u], v[u], qp);
    }
    s_qp[idx] = qp;
    g_c1[b*2048 + idx] = liw[f] * qp;
  }
  __syncthreads();
  if (t < NSLOT){
    float a2 = 0.f, a3 = 0.f;
    for (int f = 0; f < 256; f++){
      a2 = fmaf(liw[f], s_qp[t*256 + f], a2);
      a3 = fmaf(lib[f], s_qp[t*256 + f], a3);
    }
    g_c2[b*NSLOT + t] = a2;
    g_c3[b*NSLOT + t] = a3;
  }
}

// ---------------- launch ----------------
extern "C" void kernel_launch(void* const* d_in, const int* in_sizes, int n_in,
                              void* d_out, int out_size){
  const float* inputs   = (const float*)d_in[0];
  const float* slotinit = (const float*)d_in[1];
  const float* Wq       = (const float*)d_in[2];
  const float* Wk       = (const float*)d_in[3];
  const float* Wv       = (const float*)d_in[4];
  const float* gru_wi   = (const float*)d_in[5];
  const float* gru_wh   = (const float*)d_in[6];
  const float* gru_bi   = (const float*)d_in[7];
  const float* gru_bh   = (const float*)d_in[8];
  const float* ln_in_w  = (const float*)d_in[9];
  const float* ln_in_b  = (const float*)d_in[10];
  const float* ln_s_w   = (const float*)d_in[11];
  const float* ln_s_b   = (const float*)d_in[12];
  const float* ln_m_w   = (const float*)d_in[13];
  const float* ln_m_b   = (const float*)d_in[14];
  const float* mlp_w1   = (const float*)d_in[15];
  const float* mlp_b1   = (const float*)d_in[16];
  const float* mlp_w2   = (const float*)d_in[17];
  const float* mlp_b2   = (const float*)d_in[18];
  float* out = (float*)d_out;

  qprep0<<<NB, 384>>>(slotinit, out, Wq, Wk, ln_s_w, ln_s_b, ln_in_w, ln_in_b); // 1
  stats_k<<<(NB*NN)/8, 256>>>(inputs);                                          // 2
  dummy_k<<<1, 32>>>();                                                         // 3

  for (int it = 0; it < 3; it++){
    attn_scan<<<dim3(NB, NCH), 128>>>(inputs);   // 4th launch on it=0 (ncu)
    tail_bk<<<dim3(NB, 4), 256>>>(out, gru_wi, gru_wh, gru_bi, gru_bh,
                           ln_m_w, ln_m_b, mlp_w1, mlp_b1, mlp_w2, mlp_b2,
                           Wq, Wk, Wv, ln_s_w, ln_s_b, ln_in_w, ln_in_b,
                           (it < 2) ? 1 : 0);
  }
}